// round 10
// baseline (speedup 1.0000x reference)
#include <cuda_runtime.h>
#include <cuda_fp16.h>
#include <cstdint>

#define BB   2
#define NC   6
#define CCH  256
#define FHH  28
#define FWW  50
#define HWF  (FHH*FWW)      // 1400
#define HWP  1408           // padded M for HMMA (22 * 64)
#define PP   40000
#define ZZ   3
#define NR   (ZZ*NC)        // 18 records per (b,p)

// u_norm = u * (fW/IMG_W) / (fW-1) * 2 - 1
__device__ __constant__ float CU2 = (float)((50.0/1600.0)/49.0*2.0);
__device__ __constant__ float CV2 = (float)((28.0/900.0)/27.0*2.0);

// Scratch (zero-initialized device globals; no allocations anywhere)
__device__ __half  g_featC[(size_t)BB*NC*HWF*CCH + 64*CCH]; // fp16 conv-ed features + OOB pad (stays 0)
__device__ __half  g_featH[(size_t)BB*NC*HWP*CCH];          // fp16 feats transposed [bn][hw][c], rows>=1400 zero
__device__ __half  g_whT[CCH*CCH];                          // fp16 W transposed: whT[c][o]
__device__ int     g_idx[NR*BB*PP];                         // corner base index or -1
__device__ float4  g_w[NR*BB*PP];                           // 4 bilinear weights (pre-scaled by invc/3)
__device__ float   g_cam[BB*NC*12];                         // fused K*E_inv per camera: M[9], c[3]

// ---------------------------------------------------------------------------
// Kernel 1a: W (o,c) fp32 -> whT (c,o) fp16
// ---------------------------------------------------------------------------
__global__ void prep_w(const float* __restrict__ w)
{
    int t = blockIdx.x * 256 + threadIdx.x;   // 65536 threads
    int c = t >> 8, o = t & 255;
    g_whT[c*CCH + o] = __float2half(w[o*CCH + c]);
}

// ---------------------------------------------------------------------------
// Kernel 1b: feats [bn][c][hw] fp32 -> g_featH [bn][hw][c] fp16 (32x32 tiles)
// ---------------------------------------------------------------------------
__global__ void prep_feats(const float* __restrict__ feats)
{
    __shared__ float t[32][33];
    const int bn  = blockIdx.z;
    const int hw0 = blockIdx.x * 32;
    const int c0  = blockIdx.y * 32;
    const int tx  = threadIdx.x, ty = threadIdx.y;   // 32 x 8

    const float* src = feats + (size_t)bn * CCH * HWF;
#pragma unroll
    for (int r = 0; r < 4; r++) {
        int c  = c0 + ty + r * 8;
        int hw = hw0 + tx;
        t[ty + r*8][tx] = (hw < HWF) ? src[(size_t)c * HWF + hw] : 0.f;
    }
    __syncthreads();
    __half* dst = g_featH + (size_t)bn * HWP * CCH;
#pragma unroll
    for (int r = 0; r < 4; r++) {
        int i  = ty + r * 8;                 // local hw
        int hw = hw0 + i;                    // < 1408 always
        dst[(size_t)hw * CCH + c0 + tx] = __float2half(t[tx][i]);
    }
}

// ---------------------------------------------------------------------------
// Kernel 1c: fuse K * E_inv per camera. M = K * R^T, c = K * (-R^T t).
// One thread per (b,n).
// ---------------------------------------------------------------------------
__global__ void prep_cam(const float* __restrict__ intr,
                         const float* __restrict__ extr)
{
    int bn = threadIdx.x;
    if (bn >= BB * NC) return;
    const float* E = extr + bn * 16;
    const float* K = intr + bn * 9;

    float Rt[9];
#pragma unroll
    for (int i = 0; i < 3; i++)
#pragma unroll
        for (int j = 0; j < 3; j++)
            Rt[i*3 + j] = E[j*4 + i];
    float t0 = E[3], t1 = E[7], t2 = E[11];
    float tp[3];
#pragma unroll
    for (int i = 0; i < 3; i++)
        tp[i] = -(Rt[i*3+0]*t0 + Rt[i*3+1]*t1 + Rt[i*3+2]*t2);

    float* o = g_cam + bn * 12;
#pragma unroll
    for (int i = 0; i < 3; i++) {
#pragma unroll
        for (int j = 0; j < 3; j++)
            o[i*3 + j] = K[i*3+0]*Rt[0*3+j] + K[i*3+1]*Rt[1*3+j] + K[i*3+2]*Rt[2*3+j];
        o[9 + i] = K[i*3+0]*tp[0] + K[i*3+1]*tp[1] + K[i*3+2]*tp[2];
    }
}

// ---------------------------------------------------------------------------
// Kernel 2: HMMA GEMM per (b,n): featC[hw][o] = sum_c featH[hw][c] * W[o][c]
// BM=64, BN=256, BK=16; 8 warps = 2(m) x 4(n); warp tile m32 n64.
// mma.sync.m16n8k16 f16 x f16 -> f32. Double-buffered smem, padded strides
// (A row 24 halves, B row 264 halves) for conflict-free ldmatrix.
// ---------------------------------------------------------------------------
#define GBM 64
#define GBK 16
#define ASTR 24
#define BSTR 264

__device__ __forceinline__ uint32_t smem_u32(const void* p)
{
    return (uint32_t)__cvta_generic_to_shared(p);
}

__device__ __forceinline__ void ldm_x4(uint32_t* r, uint32_t addr)
{
    asm volatile("ldmatrix.sync.aligned.m8n8.x4.shared.b16 {%0,%1,%2,%3}, [%4];"
                 : "=r"(r[0]), "=r"(r[1]), "=r"(r[2]), "=r"(r[3]) : "r"(addr));
}
__device__ __forceinline__ void ldm_x4t(uint32_t* r, uint32_t addr)
{
    asm volatile("ldmatrix.sync.aligned.m8n8.x4.trans.shared.b16 {%0,%1,%2,%3}, [%4];"
                 : "=r"(r[0]), "=r"(r[1]), "=r"(r[2]), "=r"(r[3]) : "r"(addr));
}
__device__ __forceinline__ void mma16816(float* d, const uint32_t* a, const uint32_t* b)
{
    asm volatile("mma.sync.aligned.m16n8k16.row.col.f32.f16.f16.f32 "
                 "{%0,%1,%2,%3}, {%4,%5,%6,%7}, {%8,%9}, {%0,%1,%2,%3};"
                 : "+f"(d[0]), "+f"(d[1]), "+f"(d[2]), "+f"(d[3])
                 : "r"(a[0]), "r"(a[1]), "r"(a[2]), "r"(a[3]), "r"(b[0]), "r"(b[1]));
}

__global__ __launch_bounds__(256) void conv_hmma()
{
    const int bn = blockIdx.y;              // 0..11
    const int m0 = blockIdx.x * GBM;

    __shared__ __half As[2][GBM * ASTR];
    __shared__ __half Bs[2][GBK * BSTR];

    const int tid  = threadIdx.x;
    const int lane = tid & 31;
    const int wid  = tid >> 5;
    const int wm   = wid >> 2;              // 0..1
    const int wn   = wid & 3;               // 0..3

    const __half* A = g_featH + (size_t)bn * HWP * CCH;

    float acc[2][8][4];
#pragma unroll
    for (int i = 0; i < 2; i++)
#pragma unroll
        for (int j = 0; j < 8; j++)
#pragma unroll
            for (int q = 0; q < 4; q++) acc[i][j][q] = 0.f;

    const int ar = tid >> 1;                // A row (t<128)
    const int ah = (tid & 1) * 8;           // A half-offset

    // prologue: tile k0=0 -> buf 0
    if (tid < 128) {
        uint4 v = *(const uint4*)&A[(size_t)(m0 + ar) * CCH + ah];
        *(uint4*)&As[0][ar * ASTR + ah] = v;
    }
#pragma unroll
    for (int s = 0; s < 2; s++) {
        int v = tid + 256 * s;              // 0..511
        int row = v >> 5, c = v & 31;
        uint4 u = *(const uint4*)&g_whT[(size_t)row * CCH + c * 8];
        *(uint4*)&Bs[0][row * BSTR + c * 8] = u;
    }
    __syncthreads();

    int buf = 0;
    for (int kt = 0; kt < CCH / GBK; kt++) {
        uint4 pa;  uint4 pb[2];
        const bool more = (kt + 1 < CCH / GBK);
        if (more) {
            int k0 = (kt + 1) * GBK;
            if (tid < 128)
                pa = *(const uint4*)&A[(size_t)(m0 + ar) * CCH + k0 + ah];
#pragma unroll
            for (int s = 0; s < 2; s++) {
                int v = tid + 256 * s;
                int row = v >> 5, c = v & 31;
                pb[s] = *(const uint4*)&g_whT[(size_t)(k0 + row) * CCH + c * 8];
            }
        }

        uint32_t af[2][4];
#pragma unroll
        for (int i = 0; i < 2; i++) {
            uint32_t addr = smem_u32(&As[buf][(wm*32 + i*16 + (lane & 15)) * ASTR + (lane >> 4) * 8]);
            ldm_x4(af[i], addr);
        }
        uint32_t bf[8][2];
#pragma unroll
        for (int j4 = 0; j4 < 4; j4++) {
            uint32_t r[4];
            uint32_t addr = smem_u32(&Bs[buf][(((lane >> 3) & 1) * 8 + (lane & 7)) * BSTR
                                              + wn*64 + j4*16 + (lane >> 4) * 8]);
            ldm_x4t(r, addr);
            bf[2*j4][0]   = r[0]; bf[2*j4][1]   = r[1];
            bf[2*j4+1][0] = r[2]; bf[2*j4+1][1] = r[3];
        }
#pragma unroll
        for (int i = 0; i < 2; i++)
#pragma unroll
            for (int j = 0; j < 8; j++)
                mma16816(acc[i][j], af[i], bf[j]);

        if (more) {
            if (tid < 128)
                *(uint4*)&As[buf ^ 1][ar * ASTR + ah] = pa;
#pragma unroll
            for (int s = 0; s < 2; s++) {
                int v = tid + 256 * s;
                int row = v >> 5, c = v & 31;
                *(uint4*)&Bs[buf ^ 1][row * BSTR + c * 8] = pb[s];
            }
        }
        __syncthreads();
        buf ^= 1;
    }

    // epilogue: fp16 store into g_featC[bn][hw][o]
    __half* D = g_featC + (size_t)bn * HWF * CCH;
    const int gid = lane >> 2;              // 0..7
    const int tig = lane & 3;               // 0..3
#pragma unroll
    for (int i = 0; i < 2; i++) {
        int r0 = m0 + wm*32 + i*16 + gid;
#pragma unroll
        for (int j = 0; j < 8; j++) {
            int col = wn*64 + j*8 + tig*2;
            if (r0 < HWF) {
                __half2 h = __floats2half2_rn(acc[i][j][0], acc[i][j][1]);
                *(__half2*)&D[(size_t)r0 * CCH + col] = h;
            }
            if (r0 + 8 < HWF) {
                __half2 h = __floats2half2_rn(acc[i][j][2], acc[i][j][3]);
                *(__half2*)&D[(size_t)(r0 + 8) * CCH + col] = h;
            }
        }
    }
}

// ---------------------------------------------------------------------------
// Kernel 3: projection using fused per-camera matrices. One thread per (b,z,p).
// ---------------------------------------------------------------------------
__global__ __launch_bounds__(256) void proj_kernel(const float* __restrict__ pts)
{
    int t = blockIdx.x * blockDim.x + threadIdx.x;
    if (t >= BB * ZZ * PP) return;
    int p  = t % PP;
    int zb = t / PP;
    int z  = zb % ZZ;
    int b  = zb / ZZ;

    const float* q = pts + ((size_t)z * PP + p) * 3;
    float px = q[0], py = q[1], pz = q[2];
    float cnt = 0.f;

    int    ibuf[NC];
    float4 wbuf[NC];

#pragma unroll
    for (int n = 0; n < NC; n++) {
        const float* Cm = g_cam + (b * NC + n) * 12;
        float Zc = Cm[6]*px + Cm[7]*py + Cm[8]*pz + Cm[11];
        float inv = 1.f / (Zc + 1e-6f);
        float un = (Cm[0]*px + Cm[1]*py + Cm[2]*pz + Cm[9])  * inv * CU2 - 1.f;
        float vn = (Cm[3]*px + Cm[4]*py + Cm[5]*pz + Cm[10]) * inv * CV2 - 1.f;
        bool valid = (Zc > 0.1f) && (un >= -1.f) && (un <= 1.f) && (vn >= -1.f) && (vn <= 1.f);

        int idx = -1;
        float4 w = make_float4(0.f, 0.f, 0.f, 0.f);
        if (valid) {
            float x = (un + 1.f) * 0.5f * (float)(FWW - 1);
            float y = (vn + 1.f) * 0.5f * (float)(FHH - 1);
            float x0f = floorf(x), y0f = floorf(y);
            float wx1 = x - x0f, wy1 = y - y0f;
            float wx0 = 1.f - wx1, wy0 = 1.f - wy1;
            int x0 = (int)x0f, y0 = (int)y0f;
            w = make_float4(wx0 * wy0, wx1 * wy0, wx0 * wy1, wx1 * wy1);
            if (x0 >= FWW - 1) { w.y = 0.f; w.w = 0.f; }  // x1 out of range, weight 0
            if (y0 >= FHH - 1) { w.z = 0.f; w.w = 0.f; }
            idx = y0 * FWW + x0;
            cnt += 1.f;
        }
        ibuf[n] = idx;
        wbuf[n] = w;
    }

    float icc = (1.f / (cnt + 1e-6f)) * (1.f / 3.f);
#pragma unroll
    for (int n = 0; n < NC; n++) {
        int rp = ((z * NC + n) * BB + b) * PP + p;
        float4 w = wbuf[n];
        w.x *= icc; w.y *= icc; w.z *= icc; w.w *= icc;
        g_idx[rp] = ibuf[n];
        g_w[rp]   = w;
    }
}

// ---------------------------------------------------------------------------
// Kernel 4: fp16 sampling + BN/ReLU epilogue + coalesced transposed output.
// Identical to the best-measured R4/R6/R8 configuration EXCEPT:
//  - smem transpose stores use a per-lane rotation of channel order so each
//    STS.32 round hits 32 distinct banks (stride 257 kept; addresses
//    unchanged, only temporal order permuted -> read-out identical)
//  - record loads (g_idx, g_w) use __ldcs (streaming, no L1 pollution)
//  - final output stores use __stcs
// ---------------------------------------------------------------------------
__device__ __forceinline__ void accum8(float* a, const uint4& q, float w)
{
    const __half2* h = (const __half2*)&q;
#pragma unroll
    for (int j = 0; j < 4; j++) {
        float2 f = __half22float2(h[j]);
        a[2*j]   = fmaf(f.x, w, a[2*j]);
        a[2*j+1] = fmaf(f.y, w, a[2*j+1]);
    }
}

__global__ __launch_bounds__(256, 3) void sample_kernel(const float* __restrict__ convb,
                                                        const float* __restrict__ gamma,
                                                        const float* __restrict__ beta,
                                                        const float* __restrict__ mean,
                                                        const float* __restrict__ var,
                                                        float* __restrict__ out)
{
    __shared__ float so[16 * 257];

    const int b   = blockIdx.y;
    const int p0  = blockIdx.x * 32;
    const int tid = threadIdx.x;
    const int cg  = tid & 31;     // channel group (8 channels)
    const int ps  = tid >> 5;     // warp id = pixel sub-lane 0..7
    const int o0  = cg * 8;
    const int jrot = (cg + (cg >> 3)) & 7;   // store-order rotation

    // BN + conv bias epilogue constants (per 8 channels)
    float sc[8], bi[8];
#pragma unroll
    for (int j = 0; j < 8; j++) {
        float s = gamma[o0 + j] * rsqrtf(var[o0 + j] + 1e-5f);
        sc[j] = s;
        bi[j] = (convb[o0 + j] - mean[o0 + j]) * s + beta[o0 + j];
    }

    const uint4* fc = (const uint4*)g_featC;
    const size_t ob = (size_t)b * CCH * PP + p0;

#pragma unroll 1
    for (int chunk = 0; chunk < 2; chunk++) {
#pragma unroll 1
        for (int i = 0; i < 2; i++) {
            const int lp = i * 8 + ps;            // local pixel 0..15
            const int p  = p0 + chunk * 16 + lp;

            // Preload all 18 corner indices (independent warp-uniform loads,
            // streaming: each record read once per block)
            int idxs[NR];
#pragma unroll
            for (int r = 0; r < NR; r++)
                idxs[r] = __ldcs(&g_idx[(r * BB + b) * PP + p]);

            float a[8];
#pragma unroll
            for (int j = 0; j < 8; j++) a[j] = 0.f;

#pragma unroll
            for (int z = 0; z < ZZ; z++) {
#pragma unroll
                for (int n = 0; n < NC; n++) {
                    const int r = z * NC + n;
                    const int idx = idxs[r];
                    if (idx >= 0) {
                        float4 w = __ldcs(&g_w[(r * BB + b) * PP + p]);
                        const uint4* f = fc + ((size_t)(b * NC + n) * HWF + idx) * 32 + cg;
                        uint4 q00 = f[0];
                        uint4 q01 = f[32];
                        uint4 q10 = f[FWW * 32];
                        uint4 q11 = f[(FWW + 1) * 32];
                        accum8(a, q00, w.x);
                        accum8(a, q01, w.y);
                        accum8(a, q10, w.z);
                        accum8(a, q11, w.w);
                    }
                }
            }
            // Bank-conflict-free transpose stores: rotated temporal order,
            // canonical addresses (stride 257 == 1 mod 32; within each
            // conflict octet the rotated offsets are all distinct).
            int row = lp * 257 + o0;
#pragma unroll
            for (int jj = 0; jj < 8; jj++) {
                int j = (jj + jrot) & 7;
                so[row + j] = fmaxf(fmaf(a[j], sc[j], bi[j]), 0.f);
            }
        }
        __syncthreads();

        // Transposed write-out: 16 consecutive threads write 16 consecutive
        // pixels of one o-row (64B coalesced streaming stores).
        const int px = tid & 15;
        const int og = tid >> 4;          // 0..15
#pragma unroll
        for (int ot = 0; ot < 16; ot++) {
            int o = og + ot * 16;
            __stcs(&out[ob + (size_t)o * PP + chunk * 16 + px], so[px * 257 + o]);
        }
        __syncthreads();
    }
}

// ---------------------------------------------------------------------------
extern "C" void kernel_launch(void* const* d_in, const int* in_sizes, int n_in,
                              void* d_out, int out_size)
{
    const float* feats = (const float*)d_in[0];
    const float* intr  = (const float*)d_in[1];
    const float* extr  = (const float*)d_in[2];
    const float* pts   = (const float*)d_in[3];
    const float* convw = (const float*)d_in[4];
    const float* convb = (const float*)d_in[5];
    const float* gamma = (const float*)d_in[6];
    const float* beta  = (const float*)d_in[7];
    const float* mean  = (const float*)d_in[8];
    const float* var   = (const float*)d_in[9];
    float* out = (float*)d_out;

    prep_w<<<256, 256>>>(convw);
    prep_feats<<<dim3(HWP/32, CCH/32, BB*NC), dim3(32, 8)>>>(feats);
    prep_cam<<<1, 32>>>(intr, extr);
    conv_hmma<<<dim3(HWP/GBM, BB*NC), 256>>>();
    proj_kernel<<<(BB * ZZ * PP + 255) / 256, 256>>>(pts);
    sample_kernel<<<dim3(PP / 32, BB), 256>>>(convb, gamma, beta, mean, var, out);
}

// round 11
// speedup vs baseline: 1.1443x; 1.1443x over previous
#include <cuda_runtime.h>
#include <cuda_fp16.h>
#include <cstdint>

#define BB   2
#define NC   6
#define CCH  256
#define FHH  28
#define FWW  50
#define HWF  (FHH*FWW)      // 1400
#define HWP  1408           // padded M for HMMA (22 * 64)
#define PP   40000
#define ZZ   3
#define NR   (ZZ*NC)        // 18 record slots per (b,p)

// u_norm = u * (fW/IMG_W) / (fW-1) * 2 - 1
__device__ __constant__ float CU2 = (float)((50.0/1600.0)/49.0*2.0);
__device__ __constant__ float CV2 = (float)((28.0/900.0)/27.0*2.0);

// Scratch (zero-initialized device globals; no allocations anywhere)
__device__ __half  g_featC[(size_t)BB*NC*HWF*CCH + 64*CCH]; // fp16 conv-ed features + OOB pad (stays 0)
__device__ __half  g_featH[(size_t)BB*NC*HWP*CCH];          // fp16 feats transposed [bn][hw][c], rows>=1400 zero
__device__ __half  g_whT[CCH*CCH];                          // fp16 W transposed: whT[c][o]
__device__ int     g_cnt[BB*PP];                            // valid-record count per (b,p)
__device__ int     g_crec[BB*PP*NR + 8];                    // compacted records: full feature offset
__device__ float4  g_cw[BB*PP*NR + 8];                      // compacted weights (pre-scaled by invc/3)
__device__ float   g_cam[BB*NC*12];                         // fused K*E_inv per camera: M[9], c[3]

// ---------------------------------------------------------------------------
// Kernel 1a: W (o,c) fp32 -> whT (c,o) fp16
// ---------------------------------------------------------------------------
__global__ void prep_w(const float* __restrict__ w)
{
    int t = blockIdx.x * 256 + threadIdx.x;   // 65536 threads
    int c = t >> 8, o = t & 255;
    g_whT[c*CCH + o] = __float2half(w[o*CCH + c]);
}

// ---------------------------------------------------------------------------
// Kernel 1b: feats [bn][c][hw] fp32 -> g_featH [bn][hw][c] fp16 (32x32 tiles)
// ---------------------------------------------------------------------------
__global__ void prep_feats(const float* __restrict__ feats)
{
    __shared__ float t[32][33];
    const int bn  = blockIdx.z;
    const int hw0 = blockIdx.x * 32;
    const int c0  = blockIdx.y * 32;
    const int tx  = threadIdx.x, ty = threadIdx.y;   // 32 x 8

    const float* src = feats + (size_t)bn * CCH * HWF;
#pragma unroll
    for (int r = 0; r < 4; r++) {
        int c  = c0 + ty + r * 8;
        int hw = hw0 + tx;
        t[ty + r*8][tx] = (hw < HWF) ? src[(size_t)c * HWF + hw] : 0.f;
    }
    __syncthreads();
    __half* dst = g_featH + (size_t)bn * HWP * CCH;
#pragma unroll
    for (int r = 0; r < 4; r++) {
        int i  = ty + r * 8;                 // local hw
        int hw = hw0 + i;                    // < 1408 always
        dst[(size_t)hw * CCH + c0 + tx] = __float2half(t[tx][i]);
    }
}

// ---------------------------------------------------------------------------
// Kernel 1c: fuse K * E_inv per camera. M = K * R^T, c = K * (-R^T t).
// One thread per (b,n).
// ---------------------------------------------------------------------------
__global__ void prep_cam(const float* __restrict__ intr,
                         const float* __restrict__ extr)
{
    int bn = threadIdx.x;
    if (bn >= BB * NC) return;
    const float* E = extr + bn * 16;
    const float* K = intr + bn * 9;

    float Rt[9];
#pragma unroll
    for (int i = 0; i < 3; i++)
#pragma unroll
        for (int j = 0; j < 3; j++)
            Rt[i*3 + j] = E[j*4 + i];
    float t0 = E[3], t1 = E[7], t2 = E[11];
    float tp[3];
#pragma unroll
    for (int i = 0; i < 3; i++)
        tp[i] = -(Rt[i*3+0]*t0 + Rt[i*3+1]*t1 + Rt[i*3+2]*t2);

    float* o = g_cam + bn * 12;
#pragma unroll
    for (int i = 0; i < 3; i++) {
#pragma unroll
        for (int j = 0; j < 3; j++)
            o[i*3 + j] = K[i*3+0]*Rt[0*3+j] + K[i*3+1]*Rt[1*3+j] + K[i*3+2]*Rt[2*3+j];
        o[9 + i] = K[i*3+0]*tp[0] + K[i*3+1]*tp[1] + K[i*3+2]*tp[2];
    }
}

// ---------------------------------------------------------------------------
// Kernel 2: HMMA GEMM per (b,n): featC[hw][o] = sum_c featH[hw][c] * W[o][c]
// (unchanged from the 129us configuration)
// ---------------------------------------------------------------------------
#define GBM 64
#define GBK 16
#define ASTR 24
#define BSTR 264

__device__ __forceinline__ uint32_t smem_u32(const void* p)
{
    return (uint32_t)__cvta_generic_to_shared(p);
}

__device__ __forceinline__ void ldm_x4(uint32_t* r, uint32_t addr)
{
    asm volatile("ldmatrix.sync.aligned.m8n8.x4.shared.b16 {%0,%1,%2,%3}, [%4];"
                 : "=r"(r[0]), "=r"(r[1]), "=r"(r[2]), "=r"(r[3]) : "r"(addr));
}
__device__ __forceinline__ void ldm_x4t(uint32_t* r, uint32_t addr)
{
    asm volatile("ldmatrix.sync.aligned.m8n8.x4.trans.shared.b16 {%0,%1,%2,%3}, [%4];"
                 : "=r"(r[0]), "=r"(r[1]), "=r"(r[2]), "=r"(r[3]) : "r"(addr));
}
__device__ __forceinline__ void mma16816(float* d, const uint32_t* a, const uint32_t* b)
{
    asm volatile("mma.sync.aligned.m16n8k16.row.col.f32.f16.f16.f32 "
                 "{%0,%1,%2,%3}, {%4,%5,%6,%7}, {%8,%9}, {%0,%1,%2,%3};"
                 : "+f"(d[0]), "+f"(d[1]), "+f"(d[2]), "+f"(d[3])
                 : "r"(a[0]), "r"(a[1]), "r"(a[2]), "r"(a[3]), "r"(b[0]), "r"(b[1]));
}

__global__ __launch_bounds__(256) void conv_hmma()
{
    const int bn = blockIdx.y;              // 0..11
    const int m0 = blockIdx.x * GBM;

    __shared__ __half As[2][GBM * ASTR];
    __shared__ __half Bs[2][GBK * BSTR];

    const int tid  = threadIdx.x;
    const int lane = tid & 31;
    const int wid  = tid >> 5;
    const int wm   = wid >> 2;              // 0..1
    const int wn   = wid & 3;               // 0..3

    const __half* A = g_featH + (size_t)bn * HWP * CCH;

    float acc[2][8][4];
#pragma unroll
    for (int i = 0; i < 2; i++)
#pragma unroll
        for (int j = 0; j < 8; j++)
#pragma unroll
            for (int q = 0; q < 4; q++) acc[i][j][q] = 0.f;

    const int ar = tid >> 1;                // A row (t<128)
    const int ah = (tid & 1) * 8;           // A half-offset

    // prologue: tile k0=0 -> buf 0
    if (tid < 128) {
        uint4 v = *(const uint4*)&A[(size_t)(m0 + ar) * CCH + ah];
        *(uint4*)&As[0][ar * ASTR + ah] = v;
    }
#pragma unroll
    for (int s = 0; s < 2; s++) {
        int v = tid + 256 * s;              // 0..511
        int row = v >> 5, c = v & 31;
        uint4 u = *(const uint4*)&g_whT[(size_t)row * CCH + c * 8];
        *(uint4*)&Bs[0][row * BSTR + c * 8] = u;
    }
    __syncthreads();

    int buf = 0;
    for (int kt = 0; kt < CCH / GBK; kt++) {
        uint4 pa;  uint4 pb[2];
        const bool more = (kt + 1 < CCH / GBK);
        if (more) {
            int k0 = (kt + 1) * GBK;
            if (tid < 128)
                pa = *(const uint4*)&A[(size_t)(m0 + ar) * CCH + k0 + ah];
#pragma unroll
            for (int s = 0; s < 2; s++) {
                int v = tid + 256 * s;
                int row = v >> 5, c = v & 31;
                pb[s] = *(const uint4*)&g_whT[(size_t)(k0 + row) * CCH + c * 8];
            }
        }

        uint32_t af[2][4];
#pragma unroll
        for (int i = 0; i < 2; i++) {
            uint32_t addr = smem_u32(&As[buf][(wm*32 + i*16 + (lane & 15)) * ASTR + (lane >> 4) * 8]);
            ldm_x4(af[i], addr);
        }
        uint32_t bf[8][2];
#pragma unroll
        for (int j4 = 0; j4 < 4; j4++) {
            uint32_t r[4];
            uint32_t addr = smem_u32(&Bs[buf][(((lane >> 3) & 1) * 8 + (lane & 7)) * BSTR
                                              + wn*64 + j4*16 + (lane >> 4) * 8]);
            ldm_x4t(r, addr);
            bf[2*j4][0]   = r[0]; bf[2*j4][1]   = r[1];
            bf[2*j4+1][0] = r[2]; bf[2*j4+1][1] = r[3];
        }
#pragma unroll
        for (int i = 0; i < 2; i++)
#pragma unroll
            for (int j = 0; j < 8; j++)
                mma16816(acc[i][j], af[i], bf[j]);

        if (more) {
            if (tid < 128)
                *(uint4*)&As[buf ^ 1][ar * ASTR + ah] = pa;
#pragma unroll
            for (int s = 0; s < 2; s++) {
                int v = tid + 256 * s;
                int row = v >> 5, c = v & 31;
                *(uint4*)&Bs[buf ^ 1][row * BSTR + c * 8] = pb[s];
            }
        }
        __syncthreads();
        buf ^= 1;
    }

    // epilogue: fp16 store into g_featC[bn][hw][o]
    __half* D = g_featC + (size_t)bn * HWF * CCH;
    const int gid = lane >> 2;              // 0..7
    const int tig = lane & 3;               // 0..3
#pragma unroll
    for (int i = 0; i < 2; i++) {
        int r0 = m0 + wm*32 + i*16 + gid;
#pragma unroll
        for (int j = 0; j < 8; j++) {
            int col = wn*64 + j*8 + tig*2;
            if (r0 < HWF) {
                __half2 h = __floats2half2_rn(acc[i][j][0], acc[i][j][1]);
                *(__half2*)&D[(size_t)r0 * CCH + col] = h;
            }
            if (r0 + 8 < HWF) {
                __half2 h = __floats2half2_rn(acc[i][j][2], acc[i][j][3]);
                *(__half2*)&D[(size_t)(r0 + 8) * CCH + col] = h;
            }
        }
    }
}

// ---------------------------------------------------------------------------
// Kernel 3: projection + record COMPACTION. One thread per (b,p); loops all
// 18 (z,n) pairs, knows count per z, and writes only valid records densely:
// record = full feature offset (b*NC+n)*HWF + y0*FWW + x0, weights pre-scaled
// by invc/3. Sampler then runs a uniform-count branch-free loop.
// ---------------------------------------------------------------------------
__global__ __launch_bounds__(256) void proj_kernel(const float* __restrict__ pts)
{
    int t = blockIdx.x * blockDim.x + threadIdx.x;
    if (t >= BB * PP) return;
    int p = t % PP;
    int b = t / PP;

    const int base = (b * PP + p) * NR;
    int s = 0;

#pragma unroll
    for (int z = 0; z < ZZ; z++) {
        const float* q = pts + ((size_t)z * PP + p) * 3;
        float px = q[0], py = q[1], pz = q[2];
        float cnt = 0.f;

        int    ibuf[NC];
        float4 wbuf[NC];

#pragma unroll
        for (int n = 0; n < NC; n++) {
            const float* Cm = g_cam + (b * NC + n) * 12;
            float Zc = Cm[6]*px + Cm[7]*py + Cm[8]*pz + Cm[11];
            float inv = 1.f / (Zc + 1e-6f);
            float un = (Cm[0]*px + Cm[1]*py + Cm[2]*pz + Cm[9])  * inv * CU2 - 1.f;
            float vn = (Cm[3]*px + Cm[4]*py + Cm[5]*pz + Cm[10]) * inv * CV2 - 1.f;
            bool valid = (Zc > 0.1f) && (un >= -1.f) && (un <= 1.f) && (vn >= -1.f) && (vn <= 1.f);

            int off = -1;
            float4 w = make_float4(0.f, 0.f, 0.f, 0.f);
            if (valid) {
                float x = (un + 1.f) * 0.5f * (float)(FWW - 1);
                float y = (vn + 1.f) * 0.5f * (float)(FHH - 1);
                float x0f = floorf(x), y0f = floorf(y);
                float wx1 = x - x0f, wy1 = y - y0f;
                float wx0 = 1.f - wx1, wy0 = 1.f - wy1;
                int x0 = (int)x0f, y0 = (int)y0f;
                w = make_float4(wx0 * wy0, wx1 * wy0, wx0 * wy1, wx1 * wy1);
                if (x0 >= FWW - 1) { w.y = 0.f; w.w = 0.f; }  // x1 OOB -> weight 0
                if (y0 >= FHH - 1) { w.z = 0.f; w.w = 0.f; }
                off = (b * NC + n) * HWF + y0 * FWW + x0;
                cnt += 1.f;
            }
            ibuf[n] = off;
            wbuf[n] = w;
        }

        float icc = (1.f / (cnt + 1e-6f)) * (1.f / 3.f);
#pragma unroll
        for (int n = 0; n < NC; n++) {
            if (ibuf[n] >= 0) {
                float4 w = wbuf[n];
                w.x *= icc; w.y *= icc; w.z *= icc; w.w *= icc;
                g_crec[base + s] = ibuf[n];
                g_cw[base + s]   = w;
                s++;
            }
        }
    }
    g_cnt[b * PP + p] = s;
}

// ---------------------------------------------------------------------------
// Kernel 4: fp16 sampling + BN/ReLU epilogue + coalesced transposed output.
// Identical to the best-measured R8 config EXCEPT the record iteration:
// uniform-count compacted loop with next-record software prefetch (loads are
// warp-uniform broadcasts; trip count is warp-uniform since one warp = one
// pixel). No 18-register idx array, no invalid-record work, no branches.
// ---------------------------------------------------------------------------
__device__ __forceinline__ void accum8(float* a, const uint4& q, float w)
{
    const __half2* h = (const __half2*)&q;
#pragma unroll
    for (int j = 0; j < 4; j++) {
        float2 f = __half22float2(h[j]);
        a[2*j]   = fmaf(f.x, w, a[2*j]);
        a[2*j+1] = fmaf(f.y, w, a[2*j+1]);
    }
}

__global__ __launch_bounds__(256, 3) void sample_kernel(const float* __restrict__ convb,
                                                        const float* __restrict__ gamma,
                                                        const float* __restrict__ beta,
                                                        const float* __restrict__ mean,
                                                        const float* __restrict__ var,
                                                        float* __restrict__ out)
{
    __shared__ float so[16 * 257];

    const int b   = blockIdx.y;
    const int p0  = blockIdx.x * 32;
    const int tid = threadIdx.x;
    const int cg  = tid & 31;     // channel group (8 channels)
    const int ps  = tid >> 5;     // warp id = pixel sub-lane 0..7
    const int o0  = cg * 8;

    // BN + conv bias epilogue constants (per 8 channels)
    float sc[8], bi[8];
#pragma unroll
    for (int j = 0; j < 8; j++) {
        float s = gamma[o0 + j] * rsqrtf(var[o0 + j] + 1e-5f);
        sc[j] = s;
        bi[j] = (convb[o0 + j] - mean[o0 + j]) * s + beta[o0 + j];
    }

    const uint4* fc = (const uint4*)g_featC;
    const size_t ob = (size_t)b * CCH * PP + p0;

#pragma unroll 1
    for (int chunk = 0; chunk < 2; chunk++) {
#pragma unroll 1
        for (int i = 0; i < 2; i++) {
            const int lp = i * 8 + ps;            // local pixel 0..15
            const int p  = p0 + chunk * 16 + lp;

            const int pb   = b * PP + p;
            const int cnt  = g_cnt[pb];
            const int base = pb * NR;

            float a[8];
#pragma unroll
            for (int j = 0; j < 8; j++) a[j] = 0.f;

            // software-pipelined record loop (prefetch depth 1)
            int    off = g_crec[base];
            float4 w   = g_cw[base];
#pragma unroll 1
            for (int s = 0; s < cnt; s++) {
                int    off_n = g_crec[base + s + 1];   // padded arrays: safe
                float4 w_n   = g_cw[base + s + 1];
                const uint4* f = fc + (size_t)off * 32 + cg;
                uint4 q00 = f[0];
                uint4 q01 = f[32];
                uint4 q10 = f[FWW * 32];
                uint4 q11 = f[(FWW + 1) * 32];
                accum8(a, q00, w.x);
                accum8(a, q01, w.y);
                accum8(a, q10, w.z);
                accum8(a, q11, w.w);
                off = off_n;
                w   = w_n;
            }

            int row = lp * 257 + o0;
#pragma unroll
            for (int j = 0; j < 8; j++)
                so[row + j] = fmaxf(fmaf(a[j], sc[j], bi[j]), 0.f);
        }
        __syncthreads();

        // Transposed write-out: 16 consecutive threads write 16 consecutive
        // pixels of one o-row (64B coalesced stores).
        const int px = tid & 15;
        const int og = tid >> 4;          // 0..15
#pragma unroll
        for (int ot = 0; ot < 16; ot++) {
            int o = og + ot * 16;
            out[ob + (size_t)o * PP + chunk * 16 + px] = so[px * 257 + o];
        }
        __syncthreads();
    }
}

// ---------------------------------------------------------------------------
extern "C" void kernel_launch(void* const* d_in, const int* in_sizes, int n_in,
                              void* d_out, int out_size)
{
    const float* feats = (const float*)d_in[0];
    const float* intr  = (const float*)d_in[1];
    const float* extr  = (const float*)d_in[2];
    const float* pts   = (const float*)d_in[3];
    const float* convw = (const float*)d_in[4];
    const float* convb = (const float*)d_in[5];
    const float* gamma = (const float*)d_in[6];
    const float* beta  = (const float*)d_in[7];
    const float* mean  = (const float*)d_in[8];
    const float* var   = (const float*)d_in[9];
    float* out = (float*)d_out;

    prep_w<<<256, 256>>>(convw);
    prep_feats<<<dim3(HWP/32, CCH/32, BB*NC), dim3(32, 8)>>>(feats);
    prep_cam<<<1, 32>>>(intr, extr);
    conv_hmma<<<dim3(HWP/GBM, BB*NC), 256>>>();
    proj_kernel<<<(BB * PP + 255) / 256, 256>>>(pts);
    sample_kernel<<<dim3(PP / 32, BB), 256>>>(convb, gamma, beta, mean, var, out);
}

// round 12
// speedup vs baseline: 1.2261x; 1.0715x over previous
#include <cuda_runtime.h>
#include <cuda_fp16.h>
#include <cstdint>
#include <cstring>

#define BB   2
#define NC   6
#define CCH  256
#define FHH  28
#define FWW  50
#define HWF  (FHH*FWW)      // 1400
#define HWP  1408           // padded M for HMMA (22 * 64)
#define PP   40000
#define ZZ   3
#define NR   (ZZ*NC)        // 18 record slots per (b,p)

// u_norm = u * (fW/IMG_W) / (fW-1) * 2 - 1
__device__ __constant__ float CU2 = (float)((50.0/1600.0)/49.0*2.0);
__device__ __constant__ float CV2 = (float)((28.0/900.0)/27.0*2.0);

// Scratch (zero-initialized device globals; no allocations anywhere)
__device__ __half  g_featC[(size_t)BB*NC*HWF*CCH + 64*CCH]; // fp16 conv-ed features + OOB pad (stays 0)
__device__ __half  g_featH[(size_t)BB*NC*HWP*CCH];          // fp16 feats transposed [bn][hw][c], rows>=1400 zero
__device__ __half  g_whT[CCH*CCH];                          // fp16 W transposed: whT[c][o]
__device__ int     g_cnt[BB*PP];                            // valid-record count per (b,p)
__device__ int     g_crec[BB*PP*NR + 16];                   // compacted records: full feature offset (pad stays 0)
__device__ float4  g_cw[BB*PP*NR + 16];                     // compacted weights (pre-scaled by invc/3; pad stays 0)
__device__ float   g_cam[BB*NC*12];                         // fused K*E_inv per camera: M[9], c[3]

// ---------------------------------------------------------------------------
// Kernel 1a: W (o,c) fp32 -> whT (c,o) fp16
// ---------------------------------------------------------------------------
__global__ void prep_w(const float* __restrict__ w)
{
    int t = blockIdx.x * 256 + threadIdx.x;   // 65536 threads
    int c = t >> 8, o = t & 255;
    g_whT[c*CCH + o] = __float2half(w[o*CCH + c]);
}

// ---------------------------------------------------------------------------
// Kernel 1b: feats [bn][c][hw] fp32 -> g_featH [bn][hw][c] fp16 (32x32 tiles)
// ---------------------------------------------------------------------------
__global__ void prep_feats(const float* __restrict__ feats)
{
    __shared__ float t[32][33];
    const int bn  = blockIdx.z;
    const int hw0 = blockIdx.x * 32;
    const int c0  = blockIdx.y * 32;
    const int tx  = threadIdx.x, ty = threadIdx.y;   // 32 x 8

    const float* src = feats + (size_t)bn * CCH * HWF;
#pragma unroll
    for (int r = 0; r < 4; r++) {
        int c  = c0 + ty + r * 8;
        int hw = hw0 + tx;
        t[ty + r*8][tx] = (hw < HWF) ? src[(size_t)c * HWF + hw] : 0.f;
    }
    __syncthreads();
    __half* dst = g_featH + (size_t)bn * HWP * CCH;
#pragma unroll
    for (int r = 0; r < 4; r++) {
        int i  = ty + r * 8;                 // local hw
        int hw = hw0 + i;                    // < 1408 always
        dst[(size_t)hw * CCH + c0 + tx] = __float2half(t[tx][i]);
    }
}

// ---------------------------------------------------------------------------
// Kernel 1c: fuse K * E_inv per camera. M = K * R^T, c = K * (-R^T t).
// ---------------------------------------------------------------------------
__global__ void prep_cam(const float* __restrict__ intr,
                         const float* __restrict__ extr)
{
    int bn = threadIdx.x;
    if (bn >= BB * NC) return;
    const float* E = extr + bn * 16;
    const float* K = intr + bn * 9;

    float Rt[9];
#pragma unroll
    for (int i = 0; i < 3; i++)
#pragma unroll
        for (int j = 0; j < 3; j++)
            Rt[i*3 + j] = E[j*4 + i];
    float t0 = E[3], t1 = E[7], t2 = E[11];
    float tp[3];
#pragma unroll
    for (int i = 0; i < 3; i++)
        tp[i] = -(Rt[i*3+0]*t0 + Rt[i*3+1]*t1 + Rt[i*3+2]*t2);

    float* o = g_cam + bn * 12;
#pragma unroll
    for (int i = 0; i < 3; i++) {
#pragma unroll
        for (int j = 0; j < 3; j++)
            o[i*3 + j] = K[i*3+0]*Rt[0*3+j] + K[i*3+1]*Rt[1*3+j] + K[i*3+2]*Rt[2*3+j];
        o[9 + i] = K[i*3+0]*tp[0] + K[i*3+1]*tp[1] + K[i*3+2]*tp[2];
    }
}

// ---------------------------------------------------------------------------
// Kernel 2: HMMA GEMM per (b,n) (unchanged from the 127us configuration)
// ---------------------------------------------------------------------------
#define GBM 64
#define GBK 16
#define ASTR 24
#define BSTR 264

__device__ __forceinline__ uint32_t smem_u32(const void* p)
{
    return (uint32_t)__cvta_generic_to_shared(p);
}

__device__ __forceinline__ void ldm_x4(uint32_t* r, uint32_t addr)
{
    asm volatile("ldmatrix.sync.aligned.m8n8.x4.shared.b16 {%0,%1,%2,%3}, [%4];"
                 : "=r"(r[0]), "=r"(r[1]), "=r"(r[2]), "=r"(r[3]) : "r"(addr));
}
__device__ __forceinline__ void ldm_x4t(uint32_t* r, uint32_t addr)
{
    asm volatile("ldmatrix.sync.aligned.m8n8.x4.trans.shared.b16 {%0,%1,%2,%3}, [%4];"
                 : "=r"(r[0]), "=r"(r[1]), "=r"(r[2]), "=r"(r[3]) : "r"(addr));
}
__device__ __forceinline__ void mma16816(float* d, const uint32_t* a, const uint32_t* b)
{
    asm volatile("mma.sync.aligned.m16n8k16.row.col.f32.f16.f16.f32 "
                 "{%0,%1,%2,%3}, {%4,%5,%6,%7}, {%8,%9}, {%0,%1,%2,%3};"
                 : "+f"(d[0]), "+f"(d[1]), "+f"(d[2]), "+f"(d[3])
                 : "r"(a[0]), "r"(a[1]), "r"(a[2]), "r"(a[3]), "r"(b[0]), "r"(b[1]));
}

__global__ __launch_bounds__(256) void conv_hmma()
{
    const int bn = blockIdx.y;              // 0..11
    const int m0 = blockIdx.x * GBM;

    __shared__ __half As[2][GBM * ASTR];
    __shared__ __half Bs[2][GBK * BSTR];

    const int tid  = threadIdx.x;
    const int lane = tid & 31;
    const int wid  = tid >> 5;
    const int wm   = wid >> 2;              // 0..1
    const int wn   = wid & 3;               // 0..3

    const __half* A = g_featH + (size_t)bn * HWP * CCH;

    float acc[2][8][4];
#pragma unroll
    for (int i = 0; i < 2; i++)
#pragma unroll
        for (int j = 0; j < 8; j++)
#pragma unroll
            for (int q = 0; q < 4; q++) acc[i][j][q] = 0.f;

    const int ar = tid >> 1;                // A row (t<128)
    const int ah = (tid & 1) * 8;           // A half-offset

    if (tid < 128) {
        uint4 v = *(const uint4*)&A[(size_t)(m0 + ar) * CCH + ah];
        *(uint4*)&As[0][ar * ASTR + ah] = v;
    }
#pragma unroll
    for (int s = 0; s < 2; s++) {
        int v = tid + 256 * s;              // 0..511
        int row = v >> 5, c = v & 31;
        uint4 u = *(const uint4*)&g_whT[(size_t)row * CCH + c * 8];
        *(uint4*)&Bs[0][row * BSTR + c * 8] = u;
    }
    __syncthreads();

    int buf = 0;
    for (int kt = 0; kt < CCH / GBK; kt++) {
        uint4 pa;  uint4 pb[2];
        const bool more = (kt + 1 < CCH / GBK);
        if (more) {
            int k0 = (kt + 1) * GBK;
            if (tid < 128)
                pa = *(const uint4*)&A[(size_t)(m0 + ar) * CCH + k0 + ah];
#pragma unroll
            for (int s = 0; s < 2; s++) {
                int v = tid + 256 * s;
                int row = v >> 5, c = v & 31;
                pb[s] = *(const uint4*)&g_whT[(size_t)(k0 + row) * CCH + c * 8];
            }
        }

        uint32_t af[2][4];
#pragma unroll
        for (int i = 0; i < 2; i++) {
            uint32_t addr = smem_u32(&As[buf][(wm*32 + i*16 + (lane & 15)) * ASTR + (lane >> 4) * 8]);
            ldm_x4(af[i], addr);
        }
        uint32_t bf[8][2];
#pragma unroll
        for (int j4 = 0; j4 < 4; j4++) {
            uint32_t r[4];
            uint32_t addr = smem_u32(&Bs[buf][(((lane >> 3) & 1) * 8 + (lane & 7)) * BSTR
                                              + wn*64 + j4*16 + (lane >> 4) * 8]);
            ldm_x4t(r, addr);
            bf[2*j4][0]   = r[0]; bf[2*j4][1]   = r[1];
            bf[2*j4+1][0] = r[2]; bf[2*j4+1][1] = r[3];
        }
#pragma unroll
        for (int i = 0; i < 2; i++)
#pragma unroll
            for (int j = 0; j < 8; j++)
                mma16816(acc[i][j], af[i], bf[j]);

        if (more) {
            if (tid < 128)
                *(uint4*)&As[buf ^ 1][ar * ASTR + ah] = pa;
#pragma unroll
            for (int s = 0; s < 2; s++) {
                int v = tid + 256 * s;
                int row = v >> 5, c = v & 31;
                *(uint4*)&Bs[buf ^ 1][row * BSTR + c * 8] = pb[s];
            }
        }
        __syncthreads();
        buf ^= 1;
    }

    __half* D = g_featC + (size_t)bn * HWF * CCH;
    const int gid = lane >> 2;              // 0..7
    const int tig = lane & 3;               // 0..3
#pragma unroll
    for (int i = 0; i < 2; i++) {
        int r0 = m0 + wm*32 + i*16 + gid;
#pragma unroll
        for (int j = 0; j < 8; j++) {
            int col = wn*64 + j*8 + tig*2;
            if (r0 < HWF) {
                __half2 h = __floats2half2_rn(acc[i][j][0], acc[i][j][1]);
                *(__half2*)&D[(size_t)r0 * CCH + col] = h;
            }
            if (r0 + 8 < HWF) {
                __half2 h = __floats2half2_rn(acc[i][j][2], acc[i][j][3]);
                *(__half2*)&D[(size_t)(r0 + 8) * CCH + col] = h;
            }
        }
    }
}

// ---------------------------------------------------------------------------
// Kernel 3: projection + record compaction (unchanged from 127us config)
// ---------------------------------------------------------------------------
__global__ __launch_bounds__(256) void proj_kernel(const float* __restrict__ pts)
{
    int t = blockIdx.x * blockDim.x + threadIdx.x;
    if (t >= BB * PP) return;
    int p = t % PP;
    int b = t / PP;

    const int base = (b * PP + p) * NR;
    int s = 0;

#pragma unroll
    for (int z = 0; z < ZZ; z++) {
        const float* q = pts + ((size_t)z * PP + p) * 3;
        float px = q[0], py = q[1], pz = q[2];
        float cnt = 0.f;

        int    ibuf[NC];
        float4 wbuf[NC];

#pragma unroll
        for (int n = 0; n < NC; n++) {
            const float* Cm = g_cam + (b * NC + n) * 12;
            float Zc = Cm[6]*px + Cm[7]*py + Cm[8]*pz + Cm[11];
            float inv = 1.f / (Zc + 1e-6f);
            float un = (Cm[0]*px + Cm[1]*py + Cm[2]*pz + Cm[9])  * inv * CU2 - 1.f;
            float vn = (Cm[3]*px + Cm[4]*py + Cm[5]*pz + Cm[10]) * inv * CV2 - 1.f;
            bool valid = (Zc > 0.1f) && (un >= -1.f) && (un <= 1.f) && (vn >= -1.f) && (vn <= 1.f);

            int off = -1;
            float4 w = make_float4(0.f, 0.f, 0.f, 0.f);
            if (valid) {
                float x = (un + 1.f) * 0.5f * (float)(FWW - 1);
                float y = (vn + 1.f) * 0.5f * (float)(FHH - 1);
                float x0f = floorf(x), y0f = floorf(y);
                float wx1 = x - x0f, wy1 = y - y0f;
                float wx0 = 1.f - wx1, wy0 = 1.f - wy1;
                int x0 = (int)x0f, y0 = (int)y0f;
                w = make_float4(wx0 * wy0, wx1 * wy0, wx0 * wy1, wx1 * wy1);
                if (x0 >= FWW - 1) { w.y = 0.f; w.w = 0.f; }  // x1 OOB -> weight 0
                if (y0 >= FHH - 1) { w.z = 0.f; w.w = 0.f; }
                off = (b * NC + n) * HWF + y0 * FWW + x0;
                cnt += 1.f;
            }
            ibuf[n] = off;
            wbuf[n] = w;
        }

        float icc = (1.f / (cnt + 1e-6f)) * (1.f / 3.f);
#pragma unroll
        for (int n = 0; n < NC; n++) {
            if (ibuf[n] >= 0) {
                float4 w = wbuf[n];
                w.x *= icc; w.y *= icc; w.z *= icc; w.w *= icc;
                g_crec[base + s] = ibuf[n];
                g_cw[base + s]   = w;
                s++;
            }
        }
    }
    g_cnt[b * PP + p] = s;
}

// ---------------------------------------------------------------------------
// Kernel 4: fp16 sampling, software-pipelined corner loads + packed f32x2
// accumulation + BN/ReLU epilogue (scale/bias from smem) + transposed output.
// ---------------------------------------------------------------------------
__device__ __forceinline__ unsigned long long pack2f(float w)
{
    unsigned long long r;
    uint32_t u = __float_as_uint(w);
    asm("mov.b64 %0, {%1, %1};" : "=l"(r) : "r"(u));
    return r;
}

// acc: 4 packed float2 accumulators; q: 8 halves; w2: packed (w,w)
__device__ __forceinline__ void accum8x2(unsigned long long* acc, const uint4& q,
                                         unsigned long long w2)
{
    const __half2* h = (const __half2*)&q;
#pragma unroll
    for (int j = 0; j < 4; j++) {
        float2 f = __half22float2(h[j]);
        unsigned long long fu;
        memcpy(&fu, &f, 8);
        asm("fma.rn.f32x2 %0, %1, %2, %0;" : "+l"(acc[j]) : "l"(fu), "l"(w2));
    }
}

__global__ __launch_bounds__(256, 3) void sample_kernel(const float* __restrict__ convb,
                                                        const float* __restrict__ gamma,
                                                        const float* __restrict__ beta,
                                                        const float* __restrict__ mean,
                                                        const float* __restrict__ var,
                                                        float* __restrict__ out)
{
    __shared__ float so[16 * 257];
    __shared__ float ssc[CCH], sbi[CCH];

    const int b   = blockIdx.y;
    const int p0  = blockIdx.x * 32;
    const int tid = threadIdx.x;
    const int cg  = tid & 31;     // channel group (8 channels)
    const int ps  = tid >> 5;     // warp id = pixel sub-lane 0..7
    const int o0  = cg * 8;

    // BN + conv bias epilogue constants -> smem (one channel per thread)
    {
        float s = gamma[tid] * rsqrtf(var[tid] + 1e-5f);
        ssc[tid] = s;
        sbi[tid] = (convb[tid] - mean[tid]) * s + beta[tid];
    }
    __syncthreads();

    const uint4* fc = (const uint4*)g_featC;
    const size_t ob = (size_t)b * CCH * PP + p0;

#pragma unroll 1
    for (int chunk = 0; chunk < 2; chunk++) {
#pragma unroll 1
        for (int i = 0; i < 2; i++) {
            const int lp = i * 8 + ps;            // local pixel 0..15
            const int p  = p0 + chunk * 16 + lp;

            const int pb   = b * PP + p;
            const int cnt  = g_cnt[pb];
            const int base = pb * NR;

            unsigned long long acc[4] = {0ull, 0ull, 0ull, 0ull};

            // Pipeline prologue: meta for records 0,1; corner data for record 0.
            // Slots >= cnt are zero (never written) -> offset 0, weight 0: the
            // loads are benign and never accumulated.
            float4 w0   = g_cw[base];
            int    off1 = g_crec[base + 1];
            float4 w1   = g_cw[base + 1];
            {
                const uint4* f = fc + (size_t)g_crec[base] * 32 + cg;
                uint4 t0 = f[0], t1 = f[32], t2 = f[FWW * 32], t3 = f[(FWW + 1) * 32];
                acc[0] = 0; // keep compiler from reordering weirdness
                // stash in pipeline registers:
                uint4 q0 = t0, q1 = t1, q2 = t2, q3 = t3;

#pragma unroll 1
                for (int s = 0; s < cnt; s++) {
                    // fetch meta 2 ahead
                    int    off2 = g_crec[base + s + 2];
                    float4 w2v  = g_cw[base + s + 2];
                    // issue corner loads for record s+1 (off1 already resident)
                    const uint4* fn = fc + (size_t)off1 * 32 + cg;
                    uint4 n0 = fn[0], n1 = fn[32], n2 = fn[FWW * 32], n3 = fn[(FWW + 1) * 32];
                    // accumulate record s (loads issued one iteration ago)
                    accum8x2(acc, q0, pack2f(w0.x));
                    accum8x2(acc, q1, pack2f(w0.y));
                    accum8x2(acc, q2, pack2f(w0.z));
                    accum8x2(acc, q3, pack2f(w0.w));
                    // shift pipeline
                    q0 = n0; q1 = n1; q2 = n2; q3 = n3;
                    w0 = w1; w1 = w2v; off1 = off2;
                }
            }

            float ao[8];
            memcpy(ao, acc, 32);
            int row = lp * 257 + o0;
#pragma unroll
            for (int j = 0; j < 8; j++)
                so[row + j] = fmaxf(fmaf(ao[j], ssc[o0 + j], sbi[o0 + j]), 0.f);
        }
        __syncthreads();

        // Transposed write-out: 16 consecutive threads write 16 consecutive
        // pixels of one o-row (64B coalesced stores).
        const int px = tid & 15;
        const int og = tid >> 4;          // 0..15
#pragma unroll
        for (int ot = 0; ot < 16; ot++) {
            int o = og + ot * 16;
            out[ob + (size_t)o * PP + chunk * 16 + px] = so[px * 257 + o];
        }
        __syncthreads();
    }
}

// ---------------------------------------------------------------------------
extern "C" void kernel_launch(void* const* d_in, const int* in_sizes, int n_in,
                              void* d_out, int out_size)
{
    const float* feats = (const float*)d_in[0];
    const float* intr  = (const float*)d_in[1];
    const float* extr  = (const float*)d_in[2];
    const float* pts   = (const float*)d_in[3];
    const float* convw = (const float*)d_in[4];
    const float* convb = (const float*)d_in[5];
    const float* gamma = (const float*)d_in[6];
    const float* beta  = (const float*)d_in[7];
    const float* mean  = (const float*)d_in[8];
    const float* var   = (const float*)d_in[9];
    float* out = (float*)d_out;

    prep_w<<<256, 256>>>(convw);
    prep_feats<<<dim3(HWP/32, CCH/32, BB*NC), dim3(32, 8)>>>(feats);
    prep_cam<<<1, 32>>>(intr, extr);
    conv_hmma<<<dim3(HWP/GBM, BB*NC), 256>>>();
    proj_kernel<<<(BB * PP + 255) / 256, 256>>>(pts);
    sample_kernel<<<dim3(PP / 32, BB), 256>>>(convb, gamma, beta, mean, var, out);
}